// round 4
// baseline (speedup 1.0000x reference)
#include <cuda_runtime.h>

// TokenMixer: out = x_pos * (1 - sigmoid(cos_sim_C(x_pre, x_pos)))
// Shapes: [N=4096, B=16, C=512] fp32, row-contiguous along C.
// One warp per (n, b) row, persistent grid-stride over rows.
// C = 512 floats = 128 float4 = 4 float4 per lane.

static constexpr int C_F4_PER_LANE = 4;   // 512 / 4 / 32
static constexpr int BLOCK = 256;
static constexpr int WARPS_PER_CTA = BLOCK / 32;

__global__ __launch_bounds__(BLOCK, 8)
void tokenmixer_kernel(const float4* __restrict__ pre,
                       const float4* __restrict__ pos,
                       float4* __restrict__ out,
                       int nrows)
{
    const int lane   = threadIdx.x & 31;
    const int warp0  = blockIdx.x * WARPS_PER_CTA + (threadIdx.x >> 5);
    const int nwarps = gridDim.x * WARPS_PER_CTA;

    for (int row = warp0; row < nrows; row += nwarps) {
        const size_t base = (size_t)row * 128;  // 128 float4 per row
        const float4* a = pre + base + lane;
        const float4* b = pos + base + lane;

        // Front-batch all loads for max MLP (8 LDG.128 in flight per lane).
        // Streaming (evict-first) hints: data is touch-once.
        float4 av[C_F4_PER_LANE], bv[C_F4_PER_LANE];
#pragma unroll
        for (int i = 0; i < C_F4_PER_LANE; i++) {
            av[i] = __ldcs(a + i * 32);
            bv[i] = __ldcs(b + i * 32);
        }

        float dot = 0.f, na = 0.f, nb = 0.f;
#pragma unroll
        for (int i = 0; i < C_F4_PER_LANE; i++) {
            dot = fmaf(av[i].x, bv[i].x, dot);
            dot = fmaf(av[i].y, bv[i].y, dot);
            dot = fmaf(av[i].z, bv[i].z, dot);
            dot = fmaf(av[i].w, bv[i].w, dot);
            na  = fmaf(av[i].x, av[i].x, na);
            na  = fmaf(av[i].y, av[i].y, na);
            na  = fmaf(av[i].z, av[i].z, na);
            na  = fmaf(av[i].w, av[i].w, na);
            nb  = fmaf(bv[i].x, bv[i].x, nb);
            nb  = fmaf(bv[i].y, bv[i].y, nb);
            nb  = fmaf(bv[i].z, bv[i].z, nb);
            nb  = fmaf(bv[i].w, bv[i].w, nb);
        }

        // Warp tree reduction.
#pragma unroll
        for (int off = 16; off > 0; off >>= 1) {
            dot += __shfl_xor_sync(0xFFFFFFFFu, dot, off);
            na  += __shfl_xor_sync(0xFFFFFFFFu, na,  off);
            nb  += __shfl_xor_sync(0xFFFFFFFFu, nb,  off);
        }

        const float EPS = 1e-12f;
        float denom = fmaxf(sqrtf(na), EPS) * fmaxf(sqrtf(nb), EPS);
        float d = dot / denom;
        // 1 - sigmoid(d) = 1 / (1 + exp(d))
        float w = 1.0f / (1.0f + expf(d));

        float4* o = out + base + lane;
#pragma unroll
        for (int i = 0; i < C_F4_PER_LANE; i++) {
            float4 o4;
            o4.x = bv[i].x * w;
            o4.y = bv[i].y * w;
            o4.z = bv[i].z * w;
            o4.w = bv[i].w * w;
            __stcs(o + i * 32, o4);
        }
    }
}

extern "C" void kernel_launch(void* const* d_in, const int* in_sizes, int n_in,
                              void* d_out, int out_size)
{
    const float4* pre = (const float4*)d_in[0];
    const float4* pos = (const float4*)d_in[1];
    float4* out = (float4*)d_out;

    int nrows = in_sizes[0] / 512;           // 65536 rows
    // Persistent grid: exactly one full wave (148 SMs x 8 CTAs/SM @ 256 thr, 32 regs).
    int blocks = 148 * 8;
    if (blocks * WARPS_PER_CTA > nrows)
        blocks = (nrows + WARPS_PER_CTA - 1) / WARPS_PER_CTA;

    tokenmixer_kernel<<<blocks, BLOCK>>>(pre, pos, out, nrows);
}

// round 5
// speedup vs baseline: 1.0538x; 1.0538x over previous
#include <cuda_runtime.h>

// TokenMixer: out = x_pos * (1 - sigmoid(cos_sim_C(x_pre, x_pos)))
// Shapes: [N=4096, B=16, C=512] fp32, row-contiguous along C.
// One warp per (n, b) row, one row per warp (no grid-stride loop: keeps all
// 8 LDG.128 per lane front-batched with no loop-carried register reuse).
// C = 512 floats = 128 float4 = 4 float4 per lane.
//
// Measured (R2): 55.1us kernel @ 7.3 TB/s effective (~91% of HBM spec) —
// this is the memory-roofline configuration. R4's persistent grid +
// __ldcs/__stcs regressed to 71% DRAM; reverted.

static constexpr int C_F4_PER_LANE = 4;   // 512 / 4 / 32

__global__ __launch_bounds__(256, 8)
void tokenmixer_kernel(const float4* __restrict__ pre,
                       const float4* __restrict__ pos,
                       float4* __restrict__ out,
                       int nrows)
{
    const int gwarp = (blockIdx.x * blockDim.x + threadIdx.x) >> 5;
    const int lane  = threadIdx.x & 31;
    if (gwarp >= nrows) return;

    const size_t base = (size_t)gwarp * 128;  // 128 float4 per row
    const float4* a = pre + base;
    const float4* b = pos + base;

    // Front-batch all loads for max MLP (8 LDG.128 in flight per lane).
    float4 av[C_F4_PER_LANE], bv[C_F4_PER_LANE];
#pragma unroll
    for (int i = 0; i < C_F4_PER_LANE; i++) {
        av[i] = a[lane + i * 32];
        bv[i] = b[lane + i * 32];
    }

    float dot = 0.f, na = 0.f, nb = 0.f;
#pragma unroll
    for (int i = 0; i < C_F4_PER_LANE; i++) {
        dot = fmaf(av[i].x, bv[i].x, dot);
        dot = fmaf(av[i].y, bv[i].y, dot);
        dot = fmaf(av[i].z, bv[i].z, dot);
        dot = fmaf(av[i].w, bv[i].w, dot);
        na  = fmaf(av[i].x, av[i].x, na);
        na  = fmaf(av[i].y, av[i].y, na);
        na  = fmaf(av[i].z, av[i].z, na);
        na  = fmaf(av[i].w, av[i].w, na);
        nb  = fmaf(bv[i].x, bv[i].x, nb);
        nb  = fmaf(bv[i].y, bv[i].y, nb);
        nb  = fmaf(bv[i].z, bv[i].z, nb);
        nb  = fmaf(bv[i].w, bv[i].w, nb);
    }

    // Warp tree reduction.
#pragma unroll
    for (int off = 16; off > 0; off >>= 1) {
        dot += __shfl_xor_sync(0xFFFFFFFFu, dot, off);
        na  += __shfl_xor_sync(0xFFFFFFFFu, na,  off);
        nb  += __shfl_xor_sync(0xFFFFFFFFu, nb,  off);
    }

    const float EPS = 1e-12f;
    float denom = fmaxf(sqrtf(na), EPS) * fmaxf(sqrtf(nb), EPS);
    float d = dot / denom;
    // 1 - sigmoid(d) = 1 / (1 + exp(d))
    float w = 1.0f / (1.0f + expf(d));

#pragma unroll
    for (int i = 0; i < C_F4_PER_LANE; i++) {
        float4 o4;
        o4.x = bv[i].x * w;
        o4.y = bv[i].y * w;
        o4.z = bv[i].z * w;
        o4.w = bv[i].w * w;
        out[base + lane + i * 32] = o4;
    }
}

extern "C" void kernel_launch(void* const* d_in, const int* in_sizes, int n_in,
                              void* d_out, int out_size)
{
    const float4* pre = (const float4*)d_in[0];
    const float4* pos = (const float4*)d_in[1];
    float4* out = (float4*)d_out;

    int nrows = in_sizes[0] / 512;           // 65536 rows
    int warps_per_block = 256 / 32;          // 8
    int blocks = (nrows + warps_per_block - 1) / warps_per_block;

    tokenmixer_kernel<<<blocks, 256>>>(pre, pos, out, nrows);
}

// round 8
// speedup vs baseline: 1.0665x; 1.0121x over previous
#include <cuda_runtime.h>

// TokenMixer: out = x_pos * (1 - sigmoid(cos_sim_C(x_pre, x_pos)))
// Shapes: [N=4096, B=16, C=512] fp32, row-contiguous along C.
// One warp per (n, b) row. C = 512 floats = 128 float4 = 4 float4 per lane.
//
// ROOFLINE NOTE: traffic is the irreducible 3 x 128 MiB = 384 MiB.
// Best measured: 55.1us kernel = 7.3 TB/s effective (~91% of HBM3e spec).
// R2 vs R5 ran identical source at 55.1 / 57.2 us -> remaining spread is
// DVFS run-to-run noise. Tested-and-rejected: persistent grid + __ldcs/__stcs
// (R4: -9pts DRAM). This is the measured-best configuration.

static constexpr int C_F4_PER_LANE = 4;   // 512 / 4 / 32

__global__ __launch_bounds__(256, 8)
void tokenmixer_kernel(const float4* __restrict__ pre,
                       const float4* __restrict__ pos,
                       float4* __restrict__ out,
                       int nrows)
{
    const int gwarp = (blockIdx.x * blockDim.x + threadIdx.x) >> 5;
    const int lane  = threadIdx.x & 31;
    if (gwarp >= nrows) return;

    const size_t base = (size_t)gwarp * 128;  // 128 float4 per row
    const float4* a = pre + base;
    const float4* b = pos + base;

    // Front-batch all loads for max MLP (8 LDG.128 in flight per lane).
    float4 av[C_F4_PER_LANE], bv[C_F4_PER_LANE];
#pragma unroll
    for (int i = 0; i < C_F4_PER_LANE; i++) {
        av[i] = a[lane + i * 32];
        bv[i] = b[lane + i * 32];
    }

    float dot = 0.f, na = 0.f, nb = 0.f;
#pragma unroll
    for (int i = 0; i < C_F4_PER_LANE; i++) {
        dot = fmaf(av[i].x, bv[i].x, dot);
        dot = fmaf(av[i].y, bv[i].y, dot);
        dot = fmaf(av[i].z, bv[i].z, dot);
        dot = fmaf(av[i].w, bv[i].w, dot);
        na  = fmaf(av[i].x, av[i].x, na);
        na  = fmaf(av[i].y, av[i].y, na);
        na  = fmaf(av[i].z, av[i].z, na);
        na  = fmaf(av[i].w, av[i].w, na);
        nb  = fmaf(bv[i].x, bv[i].x, nb);
        nb  = fmaf(bv[i].y, bv[i].y, nb);
        nb  = fmaf(bv[i].z, bv[i].z, nb);
        nb  = fmaf(bv[i].w, bv[i].w, nb);
    }

    // Warp tree reduction.
#pragma unroll
    for (int off = 16; off > 0; off >>= 1) {
        dot += __shfl_xor_sync(0xFFFFFFFFu, dot, off);
        na  += __shfl_xor_sync(0xFFFFFFFFu, na,  off);
        nb  += __shfl_xor_sync(0xFFFFFFFFu, nb,  off);
    }

    const float EPS = 1e-12f;
    float denom = fmaxf(sqrtf(na), EPS) * fmaxf(sqrtf(nb), EPS);
    float d = dot / denom;
    // 1 - sigmoid(d) = 1 / (1 + exp(d))
    float w = 1.0f / (1.0f + expf(d));

#pragma unroll
    for (int i = 0; i < C_F4_PER_LANE; i++) {
        float4 o4;
        o4.x = bv[i].x * w;
        o4.y = bv[i].y * w;
        o4.z = bv[i].z * w;
        o4.w = bv[i].w * w;
        out[base + lane + i * 32] = o4;
    }
}

extern "C" void kernel_launch(void* const* d_in, const int* in_sizes, int n_in,
                              void* d_out, int out_size)
{
    const float4* pre = (const float4*)d_in[0];
    const float4* pos = (const float4*)d_in[1];
    float4* out = (float4*)d_out;

    int nrows = in_sizes[0] / 512;           // 65536 rows
    int warps_per_block = 256 / 32;          // 8
    int blocks = (nrows + warps_per_block - 1) / warps_per_block;

    tokenmixer_kernel<<<blocks, 256>>>(pre, pos, out, nrows);
}

// round 9
// speedup vs baseline: 1.0885x; 1.0206x over previous
#include <cuda_runtime.h>

// TokenMixer: out = x_pos * (1 - sigmoid(cos_sim_C(x_pre, x_pos)))
// Shapes: [N=4096, B=16, C=512] fp32, row-contiguous along C.
// One warp per (n, b) row. C = 512 floats = 128 float4 = 4 float4 per lane.
//
// ROOFLINE NOTE (final): traffic is the irreducible 3 x 128 MiB = 384 MiB.
// Best measured: 54.4us kernel = 7.4 TB/s effective (~92% of HBM3e spec),
// DRAM pipe 81.5%. Identical source measured 54.4/55.1/57.2us across runs
// (R8/R2/R5) -> residual spread is DVFS noise, not code.
// Tested-and-rejected: persistent grid + __ldcs/__stcs (R4: -9pts DRAM,
// +9.6us). Compute pipes (fma 10%, issue 21%) and occupancy (82-87%) are
// non-binding. This is the memory-roofline configuration.

static constexpr int C_F4_PER_LANE = 4;   // 512 / 4 / 32

__global__ __launch_bounds__(256, 8)
void tokenmixer_kernel(const float4* __restrict__ pre,
                       const float4* __restrict__ pos,
                       float4* __restrict__ out,
                       int nrows)
{
    const int gwarp = (blockIdx.x * blockDim.x + threadIdx.x) >> 5;
    const int lane  = threadIdx.x & 31;
    if (gwarp >= nrows) return;

    const size_t base = (size_t)gwarp * 128;  // 128 float4 per row
    const float4* a = pre + base;
    const float4* b = pos + base;

    // Front-batch all loads for max MLP (8 LDG.128 in flight per lane).
    float4 av[C_F4_PER_LANE], bv[C_F4_PER_LANE];
#pragma unroll
    for (int i = 0; i < C_F4_PER_LANE; i++) {
        av[i] = a[lane + i * 32];
        bv[i] = b[lane + i * 32];
    }

    float dot = 0.f, na = 0.f, nb = 0.f;
#pragma unroll
    for (int i = 0; i < C_F4_PER_LANE; i++) {
        dot = fmaf(av[i].x, bv[i].x, dot);
        dot = fmaf(av[i].y, bv[i].y, dot);
        dot = fmaf(av[i].z, bv[i].z, dot);
        dot = fmaf(av[i].w, bv[i].w, dot);
        na  = fmaf(av[i].x, av[i].x, na);
        na  = fmaf(av[i].y, av[i].y, na);
        na  = fmaf(av[i].z, av[i].z, na);
        na  = fmaf(av[i].w, av[i].w, na);
        nb  = fmaf(bv[i].x, bv[i].x, nb);
        nb  = fmaf(bv[i].y, bv[i].y, nb);
        nb  = fmaf(bv[i].z, bv[i].z, nb);
        nb  = fmaf(bv[i].w, bv[i].w, nb);
    }

    // Warp tree reduction.
#pragma unroll
    for (int off = 16; off > 0; off >>= 1) {
        dot += __shfl_xor_sync(0xFFFFFFFFu, dot, off);
        na  += __shfl_xor_sync(0xFFFFFFFFu, na,  off);
        nb  += __shfl_xor_sync(0xFFFFFFFFu, nb,  off);
    }

    const float EPS = 1e-12f;
    float denom = fmaxf(sqrtf(na), EPS) * fmaxf(sqrtf(nb), EPS);
    float d = dot / denom;
    // 1 - sigmoid(d) = 1 / (1 + exp(d))
    float w = 1.0f / (1.0f + expf(d));

#pragma unroll
    for (int i = 0; i < C_F4_PER_LANE; i++) {
        float4 o4;
        o4.x = bv[i].x * w;
        o4.y = bv[i].y * w;
        o4.z = bv[i].z * w;
        o4.w = bv[i].w * w;
        out[base + lane + i * 32] = o4;
    }
}

extern "C" void kernel_launch(void* const* d_in, const int* in_sizes, int n_in,
                              void* d_out, int out_size)
{
    const float4* pre = (const float4*)d_in[0];
    const float4* pos = (const float4*)d_in[1];
    float4* out = (float4*)d_out;

    int nrows = in_sizes[0] / 512;           // 65536 rows
    int warps_per_block = 256 / 32;          // 8
    int blocks = (nrows + warps_per_block - 1) / warps_per_block;

    tokenmixer_kernel<<<blocks, 256>>>(pre, pos, out, nrows);
}

// round 12
// speedup vs baseline: 1.0930x; 1.0041x over previous
#include <cuda_runtime.h>

// TokenMixer: out = x_pos * (1 - sigmoid(cos_sim_C(x_pre, x_pos)))
// Shapes: [N=4096, B=16, C=512] fp32, row-contiguous along C.
// One warp per (n, b) row. C = 512 floats = 128 float4 = 4 float4 per lane.
//
// ROOFLINE NOTE: traffic is the irreducible 3 x 128 MiB = 384 MiB.
// Best measured (R9, default stores): 53.9us kernel = 7.4 TB/s (~92% of
// HBM3e spec), DRAM 82.3%. R2/R5/R8/R9 identical source spanned
// 53.9-57.2us -> DVFS noise band.
// This round's SINGLE-VARIABLE experiment: __stcs on the output stores only
// (write-once stream; evict-first should stop dead dirty lines from
// occupying L2 ways the read miss-streams need). Loads/grid unchanged from
// the measured-best config. R4 (persistent grid + ldcs + stcs together)
// regressed; this isolates the store hint.

static constexpr int C_F4_PER_LANE = 4;   // 512 / 4 / 32

__global__ __launch_bounds__(256, 8)
void tokenmixer_kernel(const float4* __restrict__ pre,
                       const float4* __restrict__ pos,
                       float4* __restrict__ out,
                       int nrows)
{
    const int gwarp = (blockIdx.x * blockDim.x + threadIdx.x) >> 5;
    const int lane  = threadIdx.x & 31;
    if (gwarp >= nrows) return;

    const size_t base = (size_t)gwarp * 128;  // 128 float4 per row
    const float4* a = pre + base;
    const float4* b = pos + base;

    // Front-batch all loads for max MLP (8 LDG.128 in flight per lane).
    float4 av[C_F4_PER_LANE], bv[C_F4_PER_LANE];
#pragma unroll
    for (int i = 0; i < C_F4_PER_LANE; i++) {
        av[i] = a[lane + i * 32];
        bv[i] = b[lane + i * 32];
    }

    float dot = 0.f, na = 0.f, nb = 0.f;
#pragma unroll
    for (int i = 0; i < C_F4_PER_LANE; i++) {
        dot = fmaf(av[i].x, bv[i].x, dot);
        dot = fmaf(av[i].y, bv[i].y, dot);
        dot = fmaf(av[i].z, bv[i].z, dot);
        dot = fmaf(av[i].w, bv[i].w, dot);
        na  = fmaf(av[i].x, av[i].x, na);
        na  = fmaf(av[i].y, av[i].y, na);
        na  = fmaf(av[i].z, av[i].z, na);
        na  = fmaf(av[i].w, av[i].w, na);
        nb  = fmaf(bv[i].x, bv[i].x, nb);
        nb  = fmaf(bv[i].y, bv[i].y, nb);
        nb  = fmaf(bv[i].z, bv[i].z, nb);
        nb  = fmaf(bv[i].w, bv[i].w, nb);
    }

    // Warp tree reduction.
#pragma unroll
    for (int off = 16; off > 0; off >>= 1) {
        dot += __shfl_xor_sync(0xFFFFFFFFu, dot, off);
        na  += __shfl_xor_sync(0xFFFFFFFFu, na,  off);
        nb  += __shfl_xor_sync(0xFFFFFFFFu, nb,  off);
    }

    const float EPS = 1e-12f;
    float denom = fmaxf(sqrtf(na), EPS) * fmaxf(sqrtf(nb), EPS);
    float d = dot / denom;
    // 1 - sigmoid(d) = 1 / (1 + exp(d))
    float w = 1.0f / (1.0f + expf(d));

    float4* o = out + base + lane;
#pragma unroll
    for (int i = 0; i < C_F4_PER_LANE; i++) {
        float4 o4;
        o4.x = bv[i].x * w;
        o4.y = bv[i].y * w;
        o4.z = bv[i].z * w;
        o4.w = bv[i].w * w;
        __stcs(o + i * 32, o4);
    }
}

extern "C" void kernel_launch(void* const* d_in, const int* in_sizes, int n_in,
                              void* d_out, int out_size)
{
    const float4* pre = (const float4*)d_in[0];
    const float4* pos = (const float4*)d_in[1];
    float4* out = (float4*)d_out;

    int nrows = in_sizes[0] / 512;           // 65536 rows
    int warps_per_block = 256 / 32;          // 8
    int blocks = (nrows + warps_per_block - 1) / warps_per_block;

    tokenmixer_kernel<<<blocks, 256>>>(pre, pos, out, nrows);
}